// round 11
// baseline (speedup 1.0000x reference)
#include <cuda_runtime.h>
#include <cstdint>

// Problem constants (fixed shapes from setup_inputs)
#define N_PTS   20000
#define C_FEAT  64
#define BATCH   2
#define NQ_P    2048
#define NSAMP   32
#define C_OUT   (3 + C_FEAT)          // 67
#define NQ      (BATCH * NQ_P)        // 4096
#define NC      12                    // grid cells per dim, cell = 1/12 >= radius
#define NCELLS  (NC * NC * NC)        // 1728
#define CAND_MAX 128
#define SENT    0x7FFFFFFF
#define FULLM 0xffffffffu

static const float R2F = (float)(0.08 * 0.08);

// -------- scratch (static device globals: allocation-free) --------
// Invariants at kernel_launch entry (BSS-zeroed at load, restored in-kernel
// by build_kernel each call): g_cell_cnt == 0, g_sync == 0.
__device__ int    g_cell_cnt[NCELLS];
__device__ int    g_cell_start[NCELLS + 1];
__device__ int    g_sync[3];                  // arrive1, scan-done flag, arrive2
__device__ float4 g_sorted[N_PTS];            // (x,y,z, bitcast(orig index))
__device__ float4 g_featT[N_PTS * (C_FEAT / 4)];  // transposed features, (N, C)
__device__ int    g_idx[NQ * NSAMP];          // selected (padded) sample ids

__device__ __forceinline__ int cell_of(float v) {
    int c = (int)(v * (float)NC);
    return min(max(c, 0), NC - 1);
}

// exact-match helpers: left-to-right fp32, no FMA contraction
__device__ __forceinline__ float sq3(float a, float b, float c) {
    return __fadd_rn(__fadd_rn(__fmul_rn(a, a), __fmul_rn(b, b)), __fmul_rn(c, c));
}
__device__ __forceinline__ float dot3(float ax, float ay, float az,
                                      float bx, float by, float bz) {
    return __fadd_rn(__fadd_rn(__fmul_rn(ax, bx), __fmul_rn(ay, by)), __fmul_rn(az, bz));
}

// -------- KA (side stream): transpose features (C,N) -> (N,C) --------
#define T_BLOCKS_X 625                      // ceil(20000/32)
#define T_BLOCKS   (T_BLOCKS_X * 2)         // 2 channel tiles of 32

__global__ __launch_bounds__(256) void transpose_kernel(const float* __restrict__ feat) {
    __shared__ float tile[32][33];
    float* featT = (float*)g_featT;
    int bid = blockIdx.x;
    int bx = bid % T_BLOCKS_X, by = bid / T_BLOCKS_X;
    int tx = threadIdx.x & 31, ty = threadIdx.x >> 5;   // 32 x 8
    int n  = bx * 32 + tx;
    int c0 = by * 32 + ty;
    #pragma unroll
    for (int k = 0; k < 32; k += 8) {
        int c = c0 + k;
        if (n < N_PTS && c < C_FEAT)
            tile[ty + k][tx] = feat[(size_t)c * N_PTS + n];
    }
    __syncthreads();
    int c2 = by * 32 + tx;
    int n2 = bx * 32 + ty;
    #pragma unroll
    for (int k = 0; k < 32; k += 8) {
        int n3 = n2 + k;
        if (n3 < N_PTS && c2 < C_FEAT)
            featT[(size_t)n3 * C_FEAT + c2] = tile[tx][ty + k];
    }
}

// -------- K1: fused count + scan + scatter (single launch) ------------------
// 79 blocks <= 148 SMs => all co-resident in wave 1, so device-side barriers
// via global atomics are deadlock-free. Rank is register-carried from the
// count atomic into the scatter (no second atomic). Restores all invariants.
#define BLD_THREADS 256
#define BLD_BLOCKS  ((N_PTS + BLD_THREADS - 1) / BLD_THREADS)   // 79

__global__ __launch_bounds__(BLD_THREADS) void build_kernel(const float* __restrict__ xyz) {
    __shared__ int s_last;
    __shared__ int wsum[BLD_THREADS / 32];   // 8
    __shared__ int woff2[8];

    int tid = threadIdx.x;
    int n = blockIdx.x * BLD_THREADS + tid;

    // ---- phase 1: count (rank kept in register) ----
    int cell = 0, rank = 0;
    float x = 0.f, y = 0.f, z = 0.f;
    bool live = (n < N_PTS);
    if (live) {
        x = xyz[3 * n]; y = xyz[3 * n + 1]; z = xyz[3 * n + 2];
        cell = (cell_of(z) * NC + cell_of(y)) * NC + cell_of(x);
        rank = atomicAdd(&g_cell_cnt[cell], 1);
    }
    __threadfence();
    __syncthreads();
    if (tid == 0) {
        int prev = atomicAdd(&g_sync[0], 1);
        s_last = (prev == BLD_BLOCKS - 1);
    }
    __syncthreads();

    // ---- phase 2: last-arriving block scans counts -> cell_start ----
    if (s_last) {
        int lane = tid & 31, wid = tid >> 5;
        int base = tid * 7;                       // 256*7 = 1792 >= 1728
        int v[7]; int s = 0;
        #pragma unroll
        for (int i = 0; i < 7; i++) {
            int c = base + i;
            v[i] = (c < NCELLS) ? g_cell_cnt[c] : 0;
            s += v[i];
        }
        int incl = s;
        #pragma unroll
        for (int o = 1; o < 32; o <<= 1) {
            int nb = __shfl_up_sync(FULLM, incl, o);
            if (lane >= o) incl += nb;
        }
        if (lane == 31) wsum[wid] = incl;
        __syncthreads();
        if (wid == 0 && lane < 8) {
            int ww = wsum[lane];
            int iw = ww;
            #pragma unroll
            for (int o = 1; o < 8; o <<= 1) {
                int nb = __shfl_up_sync(0xffu, iw, o);
                if (lane >= o) iw += nb;
            }
            woff2[lane] = iw - ww;
        }
        __syncthreads();
        int ex = woff2[wid] + incl - s;           // exclusive prefix, first cell
        #pragma unroll
        for (int i = 0; i < 7; i++) {
            int c = base + i;
            if (c < NCELLS) g_cell_start[c] = ex;
            ex += v[i];
        }
        if (tid == BLD_THREADS - 1) g_cell_start[NCELLS] = ex;   // = N_PTS
        __threadfence();
        __syncthreads();
        if (tid == 0) atomicExch(&g_sync[1], 1);
    } else {
        if (tid == 0) {
            while (*((volatile int*)&g_sync[1]) == 0) { __nanosleep(64); }
        }
        __syncthreads();
        __threadfence();
    }

    // ---- phase 3: scatter (no atomic; rank from phase 1) ----
    if (live) {
        int pos = g_cell_start[cell] + rank;
        g_sorted[pos] = make_float4(x, y, z, __int_as_float(n));
    }

    // ---- restore invariants for the next replay ----
    if (n < NCELLS) g_cell_cnt[n] = 0;     // safe: scan already consumed counts
    __syncthreads();
    if (tid == 0) {
        int prev = atomicAdd(&g_sync[2], 1);
        if (prev == BLD_BLOCKS - 1) {      // last block out resets sync vars
            atomicExch(&g_sync[0], 0);
            atomicExch(&g_sync[1], 0);
            atomicExch(&g_sync[2], 0);
        }
    }
}

// -------- K2: ball query (grid) + select + xyz channels, one warp/query -----
#define WPB 8
__global__ __launch_bounds__(WPB * 32) void query_kernel(
    const float* __restrict__ new_xyz,
    const float* __restrict__ xyz,
    float* __restrict__ out,
    int write_idn)
{
    __shared__ __align__(16) int cand[WPB][CAND_MAX];  // candidates -> sorted ids
    int w    = threadIdx.x >> 5;
    int lane = threadIdx.x & 31;
    int q = blockIdx.x * WPB + w;
    int b = q >> 11;            // NQ_P == 2048
    int p = q & (NQ_P - 1);

    float qx = new_xyz[3 * q], qy = new_xyz[3 * q + 1], qz = new_xyz[3 * q + 2];
    float q2 = sq3(qx, qy, qz);
    const float R2 = R2F;
    const float rp = 0.0801f;   // padded radius for cell coverage

    int x0 = max(0,      (int)floorf((qx - rp) * (float)NC));
    int x1 = min(NC - 1, (int)floorf((qx + rp) * (float)NC));
    int y0 = max(0,      (int)floorf((qy - rp) * (float)NC));
    int y1 = min(NC - 1, (int)floorf((qy + rp) * (float)NC));
    int z0 = max(0,      (int)floorf((qz - rp) * (float)NC));
    int z1 = min(NC - 1, (int)floorf((qz + rp) * (float)NC));

    // ---- prefetch all row ranges in parallel across lanes ----
    int ny    = y1 - y0 + 1;                 // <= 3
    int nrows = ny * (z1 - z0 + 1);          // <= 9
    int rs0 = 0, rs1 = 0;
    if (lane < nrows) {
        int rz = lane / ny;
        int cy = y0 + (lane - rz * ny);
        int crow = ((z0 + rz) * NC + cy) * NC;
        rs0 = g_cell_start[crow + x0];
        rs1 = g_cell_start[crow + x1 + 1];
    }

    // ---- candidate scan: collect in-ball original indices ----
    int base = 0;
    for (int r = 0; r < nrows; r++) {
        int s0 = __shfl_sync(FULLM, rs0, r);
        int s1 = __shfl_sync(FULLM, rs1, r);
        for (int j0 = s0; j0 < s1; j0 += 32) {
            int j = j0 + lane;
            bool inb = false; int pid = 0;
            if (j < s1) {
                float4 pt = g_sorted[j];
                float x2  = sq3(pt.x, pt.y, pt.z);
                float dt  = dot3(qx, qy, qz, pt.x, pt.y, pt.z);
                float d2  = __fsub_rn(__fadd_rn(q2, x2), __fmul_rn(2.0f, dt));
                inb = d2 < R2;
                pid = __float_as_int(pt.w);
            }
            unsigned m = __ballot_sync(FULLM, inb);
            if (inb) {
                int pos = base + __popc(m & ((1u << lane) - 1u));
                if (pos < CAND_MAX) cand[w][pos] = pid;
            }
            base += __popc(m);
        }
    }
    int M = min(base, CAND_MAX);
    // pad to multiple of 4 with SENT for int4 rank scan
    if (lane < 3 && M + lane < CAND_MAX) cand[w][M + lane] = SENT;
    __syncwarp();

    // ---- rank-based selection: lane owns candidates lane, lane+32, ... ----
    int v0 = (lane      < M) ? cand[w][lane]      : SENT;
    int v1 = (lane + 32 < M) ? cand[w][lane + 32] : SENT;
    int v2 = (lane + 64 < M) ? cand[w][lane + 64] : SENT;
    int v3 = (lane + 96 < M) ? cand[w][lane + 96] : SENT;

    int r0 = 0, r1 = 0, r2 = 0, r3 = 0;
    {
        const int4* cp4 = reinterpret_cast<const int4*>(cand[w]);
        int nj4 = (M + 3) >> 2;
        if (M <= 64) {
            for (int j4 = 0; j4 < nj4; j4++) {
                int4 sv = cp4[j4];
                r0 += (sv.x < v0) + (sv.y < v0) + (sv.z < v0) + (sv.w < v0);
                r1 += (sv.x < v1) + (sv.y < v1) + (sv.z < v1) + (sv.w < v1);
            }
        } else {
            for (int j4 = 0; j4 < nj4; j4++) {
                int4 sv = cp4[j4];
                r0 += (sv.x < v0) + (sv.y < v0) + (sv.z < v0) + (sv.w < v0);
                r1 += (sv.x < v1) + (sv.y < v1) + (sv.z < v1) + (sv.w < v1);
                r2 += (sv.x < v2) + (sv.y < v2) + (sv.z < v2) + (sv.w < v2);
                r3 += (sv.x < v3) + (sv.y < v3) + (sv.z < v3) + (sv.w < v3);
            }
        }
    }
    __syncwarp();   // all reads of cand done before overwrite
    // scatter: sorted ascending, slot = rank (indices unique -> ranks unique).
    // SENT entries MUST NOT scatter (fast path leaves their rank at 0).
    if (v0 != SENT && r0 < NSAMP) cand[w][r0] = v0;
    if (v1 != SENT && r1 < NSAMP) cand[w][r1] = v1;
    if (v2 != SENT && r2 < NSAMP) cand[w][r2] = v2;
    if (v3 != SENT && r3 < NSAMP) cand[w][r3] = v3;
    __syncwarp();

    int cnt   = min(M, NSAMP);
    bool valid = lane < cnt;
    int first = (cnt > 0) ? cand[w][0] : 0;
    int id    = valid ? cand[w][lane] : first;
    float idn = (valid || cnt == 0) ? 1.0f : 0.0f;

    g_idx[q * NSAMP + lane] = id;             // coalesced, consumed by K3

    // ---- xyz part (3 channels), lane = sample slot ----
    float px = xyz[3 * id], py = xyz[3 * id + 1], pz = xyz[3 * id + 2];
    size_t ob = (((size_t)b * C_OUT) * NQ_P + (size_t)p) * NSAMP + (size_t)lane;
    const size_t st = (size_t)NQ_P * NSAMP;
    out[ob]          = __fsub_rn(px, qx);
    out[ob + st]     = __fsub_rn(py, qy);
    out[ob + 2 * st] = __fsub_rn(pz, qz);

    if (write_idn) {
        size_t nfe = (size_t)BATCH * C_OUT * NQ_P * NSAMP;
        out[nfe + (size_t)q * NSAMP + lane] = idn;
    }
}

// -------- K3: feature grouping, 2 warps per query (8 float4 chunks each) ----
// Each staging LDG.128 reads a fully contiguous 128B row half (4 rows/instr),
// 8 independent gathers in flight per warp. Swizzle lc^(r&7): STS and LDS are
// conflict-free per quarter-warp.
#define GW_PB 8     // warps per block -> 1024 blocks
__global__ __launch_bounds__(GW_PB * 32) void group_kernel(float* __restrict__ out) {
    __shared__ float4 sbuf[GW_PB][NSAMP * 8];      // 4KB per warp, 32KB/block
    int w    = threadIdx.x >> 5;
    int lane = threadIdx.x & 31;
    int gw = blockIdx.x * GW_PB + w;
    int q  = gw >> 1;          // query
    int kk = gw & 1;           // half: chunks [8kk, 8kk+8) = channels [32kk,32kk+32)
    int b = q >> 11;
    int p = q & (NQ_P - 1);

    int id = g_idx[q * NSAMP + lane];              // coalesced

    float4* mybuf = sbuf[w];
    int lc = lane & 7;                 // chunk within half (0..7)
    int lr = lane >> 3;                // row base (0..3)
    #pragma unroll
    for (int t = 0; t < 8; t++) {
        int r = lr + 4 * t;
        int id_r = __shfl_sync(FULLM, id, r);
        float4 val = g_featT[(size_t)id_r * 16 + 8 * kk + lc];
        mybuf[r * 8 + (lc ^ (r & 7))] = val;
    }
    __syncwarp();

    // drain transposed: lane = sample, 32 channels -> coalesced stores
    size_t ob = (((size_t)b * C_OUT) * NQ_P + (size_t)p) * NSAMP + (size_t)lane;
    const size_t st = (size_t)NQ_P * NSAMP;
    size_t o = ob + (size_t)(3 + 32 * kk) * st;
    int myswz = lane & 7;
    #pragma unroll
    for (int j = 0; j < 8; j++) {
        float4 f = mybuf[lane * 8 + (j ^ myswz)];
        size_t oo = o + (size_t)(4 * j) * st;
        out[oo]          = f.x;
        out[oo + st]     = f.y;
        out[oo + 2 * st] = f.z;
        out[oo + 3 * st] = f.w;
    }
}

extern "C" void kernel_launch(void* const* d_in, const int* in_sizes, int n_in,
                              void* d_out, int out_size) {
    const float* xyz     = (const float*)d_in[0];   // (20000, 3)
    const float* new_xyz = (const float*)d_in[1];   // (2, 2048, 3)
    const float* feat    = (const float*)d_in[2];   // (64, 20000)
    float* out = (float*)d_out;

    long long nfe = (long long)BATCH * C_OUT * NQ_P * NSAMP;           // 18,350,080
    int write_idn = ((long long)out_size >= nfe + (long long)NQ * NSAMP) ? 1 : 0;

    cudaStream_t s2;
    cudaStreamCreateWithFlags(&s2, cudaStreamNonBlocking);
    cudaEvent_t e0, e1;
    cudaEventCreateWithFlags(&e0, cudaEventDisableTiming);
    cudaEventCreateWithFlags(&e1, cudaEventDisableTiming);

    // build first, ALONE on the GPU (co-residency for the device barrier)
    build_kernel<<<BLD_BLOCKS, BLD_THREADS>>>(xyz);

    // fork AFTER build: transpose overlaps the ~10us query window
    cudaEventRecord(e0, 0);
    cudaStreamWaitEvent(s2, e0, 0);
    transpose_kernel<<<T_BLOCKS, 256, 0, s2>>>(feat);
    cudaEventRecord(e1, s2);

    query_kernel<<<NQ / WPB, WPB * 32>>>(new_xyz, xyz, out, write_idn);

    cudaStreamWaitEvent(0, e1, 0);          // join: group needs featT
    group_kernel<<<(NQ * 2) / GW_PB, GW_PB * 32>>>(out);

    cudaEventDestroy(e0);
    cudaEventDestroy(e1);
    cudaStreamDestroy(s2);
}

// round 13
// speedup vs baseline: 1.1348x; 1.1348x over previous
#include <cuda_runtime.h>
#include <cstdint>

// Problem constants (fixed shapes from setup_inputs)
#define N_PTS   20000
#define C_FEAT  64
#define BATCH   2
#define NQ_P    2048
#define NSAMP   32
#define C_OUT   (3 + C_FEAT)          // 67
#define NQ      (BATCH * NQ_P)        // 4096
#define NC      12                    // grid cells per dim, cell = 1/12 >= radius
#define NCELLS  (NC * NC * NC)        // 1728
#define CAND_MAX 128
#define SENT    0x7FFFFFFF
#define FULLM 0xffffffffu

static const float R2F = (float)(0.08 * 0.08);

// -------- scratch (static device globals: allocation-free) --------
// Invariants at kernel_launch entry (BSS-zeroed at load, restored in-kernel
// by build_kernel each call): g_cell_cnt == 0, g_sync == 0.
__device__ int    g_cell_cnt[NCELLS];
__device__ int    g_cell_start[NCELLS + 1];
__device__ int    g_sync[3];                  // arrive1, scan-done flag, arrive2
__device__ float4 g_sorted[N_PTS];            // (x,y,z, bitcast(orig index))
__device__ float4 g_featT[N_PTS * (C_FEAT / 4)];  // transposed features, (N, C)

__device__ __forceinline__ int cell_of(float v) {
    int c = (int)(v * (float)NC);
    return min(max(c, 0), NC - 1);
}

// exact-match helpers: left-to-right fp32, no FMA contraction
__device__ __forceinline__ float sq3(float a, float b, float c) {
    return __fadd_rn(__fadd_rn(__fmul_rn(a, a), __fmul_rn(b, b)), __fmul_rn(c, c));
}
__device__ __forceinline__ float dot3(float ax, float ay, float az,
                                      float bx, float by, float bz) {
    return __fadd_rn(__fadd_rn(__fmul_rn(ax, bx), __fmul_rn(ay, by)), __fmul_rn(az, bz));
}

// -------- K1: transpose features (C,N) -> (N,C) --------
#define T_BLOCKS_X 625                      // ceil(20000/32)
#define T_BLOCKS   (T_BLOCKS_X * 2)         // 2 channel tiles of 32

__global__ __launch_bounds__(256) void transpose_kernel(const float* __restrict__ feat) {
    __shared__ float tile[32][33];
    float* featT = (float*)g_featT;
    int bid = blockIdx.x;
    int bx = bid % T_BLOCKS_X, by = bid / T_BLOCKS_X;
    int tx = threadIdx.x & 31, ty = threadIdx.x >> 5;   // 32 x 8
    int n  = bx * 32 + tx;
    int c0 = by * 32 + ty;
    #pragma unroll
    for (int k = 0; k < 32; k += 8) {
        int c = c0 + k;
        if (n < N_PTS && c < C_FEAT)
            tile[ty + k][tx] = feat[(size_t)c * N_PTS + n];
    }
    __syncthreads();
    int c2 = by * 32 + tx;
    int n2 = bx * 32 + ty;
    #pragma unroll
    for (int k = 0; k < 32; k += 8) {
        int n3 = n2 + k;
        if (n3 < N_PTS && c2 < C_FEAT)
            featT[(size_t)n3 * C_FEAT + c2] = tile[tx][ty + k];
    }
}

// -------- K2: fused count + scan + scatter (single launch) ------------------
// 79 blocks <= 148 SMs and the kernel runs alone on its stream => all blocks
// co-resident; device barriers via global atomics are deadlock-free. Rank is
// register-carried from the count atomic into the scatter (no second atomic).
#define BLD_THREADS 256
#define BLD_BLOCKS  ((N_PTS + BLD_THREADS - 1) / BLD_THREADS)   // 79

__global__ __launch_bounds__(BLD_THREADS) void build_kernel(const float* __restrict__ xyz) {
    __shared__ int s_last;
    __shared__ int wsum[BLD_THREADS / 32];   // 8
    __shared__ int woff2[8];

    int tid = threadIdx.x;
    int n = blockIdx.x * BLD_THREADS + tid;

    // ---- phase 1: count (rank kept in register) ----
    int cell = 0, rank = 0;
    float x = 0.f, y = 0.f, z = 0.f;
    bool live = (n < N_PTS);
    if (live) {
        x = xyz[3 * n]; y = xyz[3 * n + 1]; z = xyz[3 * n + 2];
        cell = (cell_of(z) * NC + cell_of(y)) * NC + cell_of(x);
        rank = atomicAdd(&g_cell_cnt[cell], 1);
    }
    __threadfence();
    __syncthreads();
    if (tid == 0) {
        int prev = atomicAdd(&g_sync[0], 1);
        s_last = (prev == BLD_BLOCKS - 1);
    }
    __syncthreads();

    // ---- phase 2: last-arriving block scans counts -> cell_start ----
    if (s_last) {
        int lane = tid & 31, wid = tid >> 5;
        int base = tid * 7;                       // 256*7 = 1792 >= 1728
        int v[7]; int s = 0;
        #pragma unroll
        for (int i = 0; i < 7; i++) {
            int c = base + i;
            v[i] = (c < NCELLS) ? g_cell_cnt[c] : 0;
            s += v[i];
        }
        int incl = s;
        #pragma unroll
        for (int o = 1; o < 32; o <<= 1) {
            int nb = __shfl_up_sync(FULLM, incl, o);
            if (lane >= o) incl += nb;
        }
        if (lane == 31) wsum[wid] = incl;
        __syncthreads();
        if (wid == 0 && lane < 8) {
            int ww = wsum[lane];
            int iw = ww;
            #pragma unroll
            for (int o = 1; o < 8; o <<= 1) {
                int nb = __shfl_up_sync(0xffu, iw, o);
                if (lane >= o) iw += nb;
            }
            woff2[lane] = iw - ww;
        }
        __syncthreads();
        int ex = woff2[wid] + incl - s;           // exclusive prefix, first cell
        #pragma unroll
        for (int i = 0; i < 7; i++) {
            int c = base + i;
            if (c < NCELLS) g_cell_start[c] = ex;
            ex += v[i];
        }
        if (tid == BLD_THREADS - 1) g_cell_start[NCELLS] = ex;   // = N_PTS
        __threadfence();
        __syncthreads();
        if (tid == 0) atomicExch(&g_sync[1], 1);
    } else {
        if (tid == 0) {
            while (*((volatile int*)&g_sync[1]) == 0) { __nanosleep(64); }
        }
        __syncthreads();
        __threadfence();
    }

    // ---- phase 3: scatter (no atomic; rank from phase 1) ----
    if (live) {
        int pos = g_cell_start[cell] + rank;
        g_sorted[pos] = make_float4(x, y, z, __int_as_float(n));
    }

    // ---- restore invariants for the next replay ----
    if (n < NCELLS) g_cell_cnt[n] = 0;     // safe: scan already consumed counts
    __syncthreads();
    if (tid == 0) {
        int prev = atomicAdd(&g_sync[2], 1);
        if (prev == BLD_BLOCKS - 1) {      // last block out resets sync vars
            atomicExch(&g_sync[0], 0);
            atomicExch(&g_sync[1], 0);
            atomicExch(&g_sync[2], 0);
        }
    }
}

// -------- K3: FUSED query + select + group. One block (128 thr) per query ---
// 4 warps scan cell rows in parallel (unordered collection; rank-sort restores
// ascending-index order since indices are unique), then each warp gathers and
// stores one 16-channel quarter via the verified swizzled smem staging.
__global__ __launch_bounds__(128) void fused_kernel(
    const float* __restrict__ new_xyz,
    const float* __restrict__ xyz,
    float* __restrict__ out,
    int write_idn)
{
    __shared__ __align__(16) int s_cand[CAND_MAX];
    __shared__ int s_ids[NSAMP];
    __shared__ int s_cnt;
    __shared__ float4 s_stage[4][NSAMP * 4];     // 2KB per warp

    int tid  = threadIdx.x;
    int w    = tid >> 5;
    int lane = tid & 31;
    int q = blockIdx.x;
    int b = q >> 11;            // NQ_P == 2048
    int p = q & (NQ_P - 1);

    float qx = new_xyz[3 * q], qy = new_xyz[3 * q + 1], qz = new_xyz[3 * q + 2];
    float q2 = sq3(qx, qy, qz);
    const float R2 = R2F;
    const float rp = 0.0801f;   // padded radius for cell coverage

    int x0 = max(0,      (int)floorf((qx - rp) * (float)NC));
    int x1 = min(NC - 1, (int)floorf((qx + rp) * (float)NC));
    int y0 = max(0,      (int)floorf((qy - rp) * (float)NC));
    int y1 = min(NC - 1, (int)floorf((qy + rp) * (float)NC));
    int z0 = max(0,      (int)floorf((qz - rp) * (float)NC));
    int z1 = min(NC - 1, (int)floorf((qz + rp) * (float)NC));

    int ny    = y1 - y0 + 1;                 // <= 3
    int nrows = ny * (z1 - z0 + 1);          // <= 9

    if (tid == 0) s_cnt = 0;
    __syncthreads();

    // ---- candidate scan: warps take rows round-robin, unordered collect ----
    for (int r = w; r < nrows; r += 4) {
        int rz = r / ny;
        int cy = y0 + (r - rz * ny);
        int crow = ((z0 + rz) * NC + cy) * NC;
        int s0 = g_cell_start[crow + x0];         // x0..x1 contiguous in sorted
        int s1 = g_cell_start[crow + x1 + 1];
        for (int j0 = s0; j0 < s1; j0 += 32) {
            int j = j0 + lane;
            bool inb = false; int pid = 0;
            if (j < s1) {
                float4 pt = g_sorted[j];
                float x2  = sq3(pt.x, pt.y, pt.z);
                float dt  = dot3(qx, qy, qz, pt.x, pt.y, pt.z);
                float d2  = __fsub_rn(__fadd_rn(q2, x2), __fmul_rn(2.0f, dt));
                inb = d2 < R2;
                pid = __float_as_int(pt.w);
            }
            unsigned m = __ballot_sync(FULLM, inb);
            int nm = __popc(m);
            int basew = 0;
            if (lane == 0 && nm) basew = atomicAdd(&s_cnt, nm);
            basew = __shfl_sync(FULLM, basew, 0);
            if (inb) {
                int pos = basew + __popc(m & ((1u << lane) - 1u));
                if (pos < CAND_MAX) s_cand[pos] = pid;
            }
        }
    }
    __syncthreads();
    int M = min(s_cnt, CAND_MAX);
    if (tid < 3 && M + tid < CAND_MAX) s_cand[M + tid] = SENT;  // pad for int4
    __syncthreads();

    // ---- rank selection: 128 threads, one candidate each ----
    int v = (tid < M) ? s_cand[tid] : SENT;
    int r = 0;
    {
        const int4* cp4 = reinterpret_cast<const int4*>(s_cand);
        int nj4 = (M + 3) >> 2;
        for (int j4 = 0; j4 < nj4; j4++) {        // broadcast reads
            int4 sv = cp4[j4];
            r += (sv.x < v) + (sv.y < v) + (sv.z < v) + (sv.w < v);
        }
    }
    __syncthreads();                              // reads done before scatter
    if (v != SENT && r < NSAMP) s_ids[r] = v;     // ranks unique (ids unique)
    __syncthreads();

    int cnt = min(M, NSAMP);

    // ---- warp 0: finalize padded ids + xyz channels + idn ----
    size_t ob0 = (((size_t)b * C_OUT) * NQ_P + (size_t)p) * NSAMP;
    const size_t st = (size_t)NQ_P * NSAMP;
    if (w == 0) {
        bool valid = lane < cnt;
        int first = (cnt > 0) ? s_ids[0] : 0;
        int id = valid ? s_ids[lane] : first;
        float idn = (valid || cnt == 0) ? 1.0f : 0.0f;
        __syncwarp();
        s_ids[lane] = id;                         // padded ids for gather warps

        float px = xyz[3 * id], py = xyz[3 * id + 1], pz = xyz[3 * id + 2];
        size_t ob = ob0 + (size_t)lane;
        out[ob]          = __fsub_rn(px, qx);
        out[ob + st]     = __fsub_rn(py, qy);
        out[ob + 2 * st] = __fsub_rn(pz, qz);
        if (write_idn) {
            size_t nfe = (size_t)BATCH * C_OUT * NQ_P * NSAMP;
            out[nfe + (size_t)q * NSAMP + lane] = idn;
        }
    }
    __syncthreads();

    // ---- feature gather: warp w -> channels [16w, 16w+16) ----
    float4* mybuf = s_stage[w];
    int lc = lane & 3;                 // chunk within quarter
    int lr = lane >> 2;                // row base
    #pragma unroll
    for (int t = 0; t < 4; t++) {
        int rr = lr + 8 * t;
        int id_r = s_ids[rr];                       // smem broadcast
        float4 val = g_featT[(size_t)id_r * 16 + 4 * w + lc];
        mybuf[rr * 4 + (lc ^ (rr & 3) ^ ((rr >> 2) & 3))] = val;
    }
    __syncwarp();

    size_t o = ob0 + (size_t)lane + 3 * st;
    int myswz = (lane & 3) ^ ((lane >> 2) & 3);
    #pragma unroll
    for (int j = 0; j < 4; j++) {
        float4 f = mybuf[lane * 4 + (j ^ myswz)];   // channels 4*(4w+j)..+3
        size_t oo = o + (size_t)(4 * (4 * w + j)) * st;
        out[oo]          = f.x;
        out[oo + st]     = f.y;
        out[oo + 2 * st] = f.z;
        out[oo + 3 * st] = f.w;
    }
}

extern "C" void kernel_launch(void* const* d_in, const int* in_sizes, int n_in,
                              void* d_out, int out_size) {
    const float* xyz     = (const float*)d_in[0];   // (20000, 3)
    const float* new_xyz = (const float*)d_in[1];   // (2, 2048, 3)
    const float* feat    = (const float*)d_in[2];   // (64, 20000)
    float* out = (float*)d_out;

    long long nfe = (long long)BATCH * C_OUT * NQ_P * NSAMP;           // 18,350,080
    int write_idn = ((long long)out_size >= nfe + (long long)NQ * NSAMP) ? 1 : 0;

    // Single stream, 3 launches, no events (tests the fork/join-floor theory).
    transpose_kernel<<<T_BLOCKS, 256>>>(feat);
    build_kernel<<<BLD_BLOCKS, BLD_THREADS>>>(xyz);
    fused_kernel<<<NQ, 128>>>(new_xyz, xyz, out, write_idn);
}

// round 16
// speedup vs baseline: 1.2406x; 1.0932x over previous
#include <cuda_runtime.h>
#include <cstdint>

// Problem constants (fixed shapes from setup_inputs)
#define N_PTS   20000
#define C_FEAT  64
#define BATCH   2
#define NQ_P    2048
#define NSAMP   32
#define C_OUT   (3 + C_FEAT)          // 67
#define NQ      (BATCH * NQ_P)        // 4096
#define NC      12                    // grid cells per dim, cell = 1/12 >= radius
#define NCELLS  (NC * NC * NC)        // 1728
#define CAND_MAX 128
#define SENT    0x7FFFFFFF
#define FULLM 0xffffffffu

static const float R2F = (float)(0.08 * 0.08);

// -------- scratch (static device globals: allocation-free) --------
// Invariants at kernel_launch entry (BSS-zeroed at load, restored in-kernel
// by prep_kernel each call): g_cell_cnt == 0, g_sync == 0.
__device__ int    g_cell_cnt[NCELLS];
__device__ int    g_cell_start[NCELLS + 1];
__device__ int    g_sync[3];                  // arrive1, scan-done flag, arrive2
__device__ float4 g_sorted[N_PTS];            // (x,y,z, bitcast(orig index))
__device__ float4 g_featT[N_PTS * (C_FEAT / 4)];  // transposed features, (N, C)

__device__ __forceinline__ int cell_of(float v) {
    int c = (int)(v * (float)NC);
    return min(max(c, 0), NC - 1);
}

// exact-match helpers: left-to-right fp32, no FMA contraction
__device__ __forceinline__ float sq3(float a, float b, float c) {
    return __fadd_rn(__fadd_rn(__fmul_rn(a, a), __fmul_rn(b, b)), __fmul_rn(c, c));
}
__device__ __forceinline__ float dot3(float ax, float ay, float az,
                                      float bx, float by, float bz) {
    return __fadd_rn(__fadd_rn(__fmul_rn(ax, bx), __fmul_rn(ay, by)), __fmul_rn(az, bz));
}

// -------- K1: MERGED build (count+scan+scatter) + feature transpose ---------
// Blocks [0, BLD_BLOCKS) run the grid build with device-side barriers;
// blocks [BLD_BLOCKS, ...) run the (C,N)->(N,C) transpose concurrently.
// Co-residency: build bids 0..78 land on distinct SMs in wave 1 (classic
// launch maps bid 0..147 across the 148 SMs), so the barrier is deadlock-free;
// transpose blocks just fill remaining slots and overlap build's latency.
#define T_BLOCKS_X 625                      // ceil(20000/32)
#define T_BLOCKS   (T_BLOCKS_X * 2)         // 2 channel tiles of 32
#define BLD_THREADS 256
#define BLD_BLOCKS  ((N_PTS + BLD_THREADS - 1) / BLD_THREADS)   // 79
#define PREP_BLOCKS (BLD_BLOCKS + T_BLOCKS)

__global__ __launch_bounds__(BLD_THREADS) void prep_kernel(
    const float* __restrict__ xyz,
    const float* __restrict__ feat)
{
    __shared__ int s_last;
    __shared__ int wsum[BLD_THREADS / 32];   // 8
    __shared__ int woff2[8];
    __shared__ float tile[32][33];

    int tid = threadIdx.x;

    if (blockIdx.x >= BLD_BLOCKS) {
        // ================= transpose tile =================
        int bid = blockIdx.x - BLD_BLOCKS;
        float* featT = (float*)g_featT;
        int bx = bid % T_BLOCKS_X, by = bid / T_BLOCKS_X;
        int tx = tid & 31, ty = tid >> 5;           // 32 x 8
        int n  = bx * 32 + tx;
        int c0 = by * 32 + ty;
        #pragma unroll
        for (int k = 0; k < 32; k += 8) {
            int c = c0 + k;
            if (n < N_PTS && c < C_FEAT)
                tile[ty + k][tx] = feat[(size_t)c * N_PTS + n];
        }
        __syncthreads();
        int c2 = by * 32 + tx;
        int n2 = bx * 32 + ty;
        #pragma unroll
        for (int k = 0; k < 32; k += 8) {
            int n3 = n2 + k;
            if (n3 < N_PTS && c2 < C_FEAT)
                featT[(size_t)n3 * C_FEAT + c2] = tile[tx][ty + k];
        }
        return;
    }

    // ================= grid build =================
    int n = blockIdx.x * BLD_THREADS + tid;

    // ---- phase 1: count (rank kept in register) ----
    int cell = 0, rank = 0;
    float x = 0.f, y = 0.f, z = 0.f;
    bool live = (n < N_PTS);
    if (live) {
        x = xyz[3 * n]; y = xyz[3 * n + 1]; z = xyz[3 * n + 2];
        cell = (cell_of(z) * NC + cell_of(y)) * NC + cell_of(x);
        rank = atomicAdd(&g_cell_cnt[cell], 1);
    }
    __threadfence();
    __syncthreads();
    if (tid == 0) {
        int prev = atomicAdd(&g_sync[0], 1);
        s_last = (prev == BLD_BLOCKS - 1);
    }
    __syncthreads();

    // ---- phase 2: last-arriving block scans counts -> cell_start ----
    if (s_last) {
        int lane = tid & 31, wid = tid >> 5;
        int base = tid * 7;                       // 256*7 = 1792 >= 1728
        int v[7]; int s = 0;
        #pragma unroll
        for (int i = 0; i < 7; i++) {
            int c = base + i;
            v[i] = (c < NCELLS) ? g_cell_cnt[c] : 0;
            s += v[i];
        }
        int incl = s;
        #pragma unroll
        for (int o = 1; o < 32; o <<= 1) {
            int nb = __shfl_up_sync(FULLM, incl, o);
            if (lane >= o) incl += nb;
        }
        if (lane == 31) wsum[wid] = incl;
        __syncthreads();
        if (wid == 0 && lane < 8) {
            int ww = wsum[lane];
            int iw = ww;
            #pragma unroll
            for (int o = 1; o < 8; o <<= 1) {
                int nb = __shfl_up_sync(0xffu, iw, o);
                if (lane >= o) iw += nb;
            }
            woff2[lane] = iw - ww;
        }
        __syncthreads();
        int ex = woff2[wid] + incl - s;           // exclusive prefix, first cell
        #pragma unroll
        for (int i = 0; i < 7; i++) {
            int c = base + i;
            if (c < NCELLS) g_cell_start[c] = ex;
            ex += v[i];
        }
        if (tid == BLD_THREADS - 1) g_cell_start[NCELLS] = ex;   // = N_PTS
        __threadfence();
        __syncthreads();
        if (tid == 0) atomicExch(&g_sync[1], 1);
    } else {
        if (tid == 0) {
            while (*((volatile int*)&g_sync[1]) == 0) { __nanosleep(64); }
        }
        __syncthreads();
        __threadfence();
    }

    // ---- phase 3: scatter (no atomic; rank from phase 1) ----
    if (live) {
        int pos = g_cell_start[cell] + rank;
        g_sorted[pos] = make_float4(x, y, z, __int_as_float(n));
    }

    // ---- restore invariants for the next replay ----
    if (n < NCELLS) g_cell_cnt[n] = 0;     // safe: scan already consumed counts
    __syncthreads();
    if (tid == 0) {
        int prev = atomicAdd(&g_sync[2], 1);
        if (prev == BLD_BLOCKS - 1) {      // last build block out resets sync
            atomicExch(&g_sync[0], 0);
            atomicExch(&g_sync[1], 0);
            atomicExch(&g_sync[2], 0);
        }
    }
}

// -------- K2: FUSED query + select + group. One block (128 thr) per query ---
// 4 warps scan cell rows in parallel (unordered collection; rank-sort restores
// ascending-index order since indices are unique), then each warp gathers and
// stores one 16-channel quarter via the verified swizzled smem staging.
__global__ __launch_bounds__(128) void fused_kernel(
    const float* __restrict__ new_xyz,
    const float* __restrict__ xyz,
    float* __restrict__ out,
    int write_idn)
{
    __shared__ __align__(16) int s_cand[CAND_MAX];
    __shared__ int s_ids[NSAMP];
    __shared__ int s_cnt;
    __shared__ float4 s_stage[4][NSAMP * 4];     // 2KB per warp

    int tid  = threadIdx.x;
    int w    = tid >> 5;
    int lane = tid & 31;
    int q = blockIdx.x;
    int b = q >> 11;            // NQ_P == 2048
    int p = q & (NQ_P - 1);

    float qx = new_xyz[3 * q], qy = new_xyz[3 * q + 1], qz = new_xyz[3 * q + 2];
    float q2 = sq3(qx, qy, qz);
    const float R2 = R2F;
    const float rp = 0.0801f;   // padded radius for cell coverage

    int x0 = max(0,      (int)floorf((qx - rp) * (float)NC));
    int x1 = min(NC - 1, (int)floorf((qx + rp) * (float)NC));
    int y0 = max(0,      (int)floorf((qy - rp) * (float)NC));
    int y1 = min(NC - 1, (int)floorf((qy + rp) * (float)NC));
    int z0 = max(0,      (int)floorf((qz - rp) * (float)NC));
    int z1 = min(NC - 1, (int)floorf((qz + rp) * (float)NC));

    int ny    = y1 - y0 + 1;                 // <= 3
    int nrows = ny * (z1 - z0 + 1);          // <= 9

    if (tid == 0) s_cnt = 0;
    __syncthreads();

    // ---- candidate scan: warps take rows round-robin, unordered collect ----
    for (int r = w; r < nrows; r += 4) {
        int rz = r / ny;
        int cy = y0 + (r - rz * ny);
        int crow = ((z0 + rz) * NC + cy) * NC;
        int s0 = g_cell_start[crow + x0];         // x0..x1 contiguous in sorted
        int s1 = g_cell_start[crow + x1 + 1];
        for (int j0 = s0; j0 < s1; j0 += 32) {
            int j = j0 + lane;
            bool inb = false; int pid = 0;
            if (j < s1) {
                float4 pt = g_sorted[j];
                float x2  = sq3(pt.x, pt.y, pt.z);
                float dt  = dot3(qx, qy, qz, pt.x, pt.y, pt.z);
                float d2  = __fsub_rn(__fadd_rn(q2, x2), __fmul_rn(2.0f, dt));
                inb = d2 < R2;
                pid = __float_as_int(pt.w);
            }
            unsigned m = __ballot_sync(FULLM, inb);
            int nm = __popc(m);
            int basew = 0;
            if (lane == 0 && nm) basew = atomicAdd(&s_cnt, nm);
            basew = __shfl_sync(FULLM, basew, 0);
            if (inb) {
                int pos = basew + __popc(m & ((1u << lane) - 1u));
                if (pos < CAND_MAX) s_cand[pos] = pid;
            }
        }
    }
    __syncthreads();
    int M = min(s_cnt, CAND_MAX);
    if (tid < 3 && M + tid < CAND_MAX) s_cand[M + tid] = SENT;  // pad for int4
    __syncthreads();

    // ---- rank selection: 128 threads, one candidate each ----
    int v = (tid < M) ? s_cand[tid] : SENT;
    int r = 0;
    {
        const int4* cp4 = reinterpret_cast<const int4*>(s_cand);
        int nj4 = (M + 3) >> 2;
        for (int j4 = 0; j4 < nj4; j4++) {        // broadcast reads
            int4 sv = cp4[j4];
            r += (sv.x < v) + (sv.y < v) + (sv.z < v) + (sv.w < v);
        }
    }
    __syncthreads();                              // reads done before scatter
    if (v != SENT && r < NSAMP) s_ids[r] = v;     // ranks unique (ids unique)
    __syncthreads();

    int cnt = min(M, NSAMP);

    // ---- warp 0: finalize padded ids + xyz channels + idn ----
    size_t ob0 = (((size_t)b * C_OUT) * NQ_P + (size_t)p) * NSAMP;
    const size_t st = (size_t)NQ_P * NSAMP;
    if (w == 0) {
        bool valid = lane < cnt;
        int first = (cnt > 0) ? s_ids[0] : 0;
        int id = valid ? s_ids[lane] : first;
        float idn = (valid || cnt == 0) ? 1.0f : 0.0f;
        __syncwarp();
        s_ids[lane] = id;                         // padded ids for gather warps

        float px = xyz[3 * id], py = xyz[3 * id + 1], pz = xyz[3 * id + 2];
        size_t ob = ob0 + (size_t)lane;
        out[ob]          = __fsub_rn(px, qx);
        out[ob + st]     = __fsub_rn(py, qy);
        out[ob + 2 * st] = __fsub_rn(pz, qz);
        if (write_idn) {
            size_t nfe = (size_t)BATCH * C_OUT * NQ_P * NSAMP;
            out[nfe + (size_t)q * NSAMP + lane] = idn;
        }
    }
    __syncthreads();

    // ---- feature gather: warp w -> channels [16w, 16w+16) ----
    float4* mybuf = s_stage[w];
    int lc = lane & 3;                 // chunk within quarter
    int lr = lane >> 2;                // row base
    #pragma unroll
    for (int t = 0; t < 4; t++) {
        int rr = lr + 8 * t;
        int id_r = s_ids[rr];                       // smem broadcast
        float4 val = g_featT[(size_t)id_r * 16 + 4 * w + lc];
        mybuf[rr * 4 + (lc ^ (rr & 3) ^ ((rr >> 2) & 3))] = val;
    }
    __syncwarp();

    size_t o = ob0 + (size_t)lane + 3 * st;
    int myswz = (lane & 3) ^ ((lane >> 2) & 3);
    #pragma unroll
    for (int j = 0; j < 4; j++) {
        float4 f = mybuf[lane * 4 + (j ^ myswz)];   // channels 4*(4w+j)..+3
        size_t oo = o + (size_t)(4 * (4 * w + j)) * st;
        out[oo]          = f.x;
        out[oo + st]     = f.y;
        out[oo + 2 * st] = f.z;
        out[oo + 3 * st] = f.w;
    }
}

extern "C" void kernel_launch(void* const* d_in, const int* in_sizes, int n_in,
                              void* d_out, int out_size) {
    const float* xyz     = (const float*)d_in[0];   // (20000, 3)
    const float* new_xyz = (const float*)d_in[1];   // (2, 2048, 3)
    const float* feat    = (const float*)d_in[2];   // (64, 20000)
    float* out = (float*)d_out;

    long long nfe = (long long)BATCH * C_OUT * NQ_P * NSAMP;           // 18,350,080
    int write_idn = ((long long)out_size >= nfe + (long long)NQ * NSAMP) ? 1 : 0;

    // Two launches: merged prep (build + transpose overlapped), then fused.
    prep_kernel<<<PREP_BLOCKS, BLD_THREADS>>>(xyz, feat);
    fused_kernel<<<NQ, 128>>>(new_xyz, xyz, out, write_idn);
}

// round 17
// speedup vs baseline: 1.2420x; 1.0012x over previous
#include <cuda_runtime.h>
#include <cstdint>

// Problem constants (fixed shapes from setup_inputs)
#define N_PTS   20000
#define C_FEAT  64
#define BATCH   2
#define NQ_P    2048
#define NSAMP   32
#define C_OUT   (3 + C_FEAT)          // 67
#define NQ      (BATCH * NQ_P)        // 4096
#define NC      12                    // grid cells per dim, cell = 1/12 >= radius
#define NCELLS  (NC * NC * NC)        // 1728
#define CAND_MAX 128
#define SENT    0x7FFFFFFF
#define FULLM 0xffffffffu

static const float R2F = (float)(0.08 * 0.08);

// -------- scratch (static device globals: allocation-free) --------
// Invariants at kernel_launch entry (BSS-zeroed at load, restored in-kernel
// by prep_kernel each call): g_cell_cnt == 0, g_sync == 0.
__device__ int    g_cell_cnt[NCELLS];
__device__ int    g_cell_start[NCELLS + 1];
__device__ int    g_sync[3];                  // arrive1, scan-done flag, arrive2
__device__ float4 g_sorted[N_PTS];            // (x,y,z, bitcast(orig index))
__device__ float4 g_featT[N_PTS * (C_FEAT / 4)];  // transposed features, (N, C)

__device__ __forceinline__ int cell_of(float v) {
    int c = (int)(v * (float)NC);
    return min(max(c, 0), NC - 1);
}

// exact-match helpers: left-to-right fp32, no FMA contraction
__device__ __forceinline__ float sq3(float a, float b, float c) {
    return __fadd_rn(__fadd_rn(__fmul_rn(a, a), __fmul_rn(b, b)), __fmul_rn(c, c));
}
__device__ __forceinline__ float dot3(float ax, float ay, float az,
                                      float bx, float by, float bz) {
    return __fadd_rn(__fadd_rn(__fmul_rn(ax, bx), __fmul_rn(ay, by)), __fmul_rn(az, bz));
}

// -------- K1: MERGED build (count+scan+scatter) + feature transpose ---------
// Blocks [0, BLD_BLOCKS) run the grid build with device-side barriers;
// blocks [BLD_BLOCKS, ...) run the (C,N)->(N,C) transpose, 4 n-tiles each.
// Grid = 393 blocks of 256 thr < co-residency capacity (148 SM x 8) => ALL
// blocks resident in wave 1; the build barrier is deadlock-free.
#define T_TILES_N  625                      // ceil(20000/32)
#define T_BATCH    4
#define T_GROUPS   ((T_TILES_N + T_BATCH - 1) / T_BATCH)   // 157
#define T_BLOCKS   (2 * T_GROUPS)           // 314 (2 channel tiles of 32)
#define BLD_THREADS 256
#define BLD_BLOCKS  ((N_PTS + BLD_THREADS - 1) / BLD_THREADS)   // 79
#define PREP_BLOCKS (BLD_BLOCKS + T_BLOCKS)

__global__ __launch_bounds__(BLD_THREADS) void prep_kernel(
    const float* __restrict__ xyz,
    const float* __restrict__ feat)
{
    __shared__ int s_last;
    __shared__ int wsum[BLD_THREADS / 32];   // 8
    __shared__ int woff2[8];
    __shared__ float tile[32][33];

    int tid = threadIdx.x;

    if (blockIdx.x >= BLD_BLOCKS) {
        // ================= transpose: 4 tiles per block =================
        int bid = blockIdx.x - BLD_BLOCKS;
        float* featT = (float*)g_featT;
        int by  = bid / T_GROUPS;                   // channel tile (0..1)
        int bg  = bid % T_GROUPS;                   // n-tile group
        int tx = tid & 31, ty = tid >> 5;           // 32 x 8
        for (int tt = 0; tt < T_BATCH; tt++) {
            int bx = bg * T_BATCH + tt;
            if (bx >= T_TILES_N) break;
            int n  = bx * 32 + tx;
            int c0 = by * 32 + ty;
            #pragma unroll
            for (int k = 0; k < 32; k += 8) {
                int c = c0 + k;
                if (n < N_PTS && c < C_FEAT)
                    tile[ty + k][tx] = feat[(size_t)c * N_PTS + n];
            }
            __syncthreads();
            int c2 = by * 32 + tx;
            int n2 = bx * 32 + ty;
            #pragma unroll
            for (int k = 0; k < 32; k += 8) {
                int n3 = n2 + k;
                if (n3 < N_PTS && c2 < C_FEAT)
                    featT[(size_t)n3 * C_FEAT + c2] = tile[tx][ty + k];
            }
            __syncthreads();            // tile reuse across iterations
        }
        return;
    }

    // ================= grid build =================
    int n = blockIdx.x * BLD_THREADS + tid;

    // ---- phase 1: count (rank kept in register) ----
    int cell = 0, rank = 0;
    float x = 0.f, y = 0.f, z = 0.f;
    bool live = (n < N_PTS);
    if (live) {
        x = xyz[3 * n]; y = xyz[3 * n + 1]; z = xyz[3 * n + 2];
        cell = (cell_of(z) * NC + cell_of(y)) * NC + cell_of(x);
        rank = atomicAdd(&g_cell_cnt[cell], 1);
    }
    __threadfence();
    __syncthreads();
    if (tid == 0) {
        int prev = atomicAdd(&g_sync[0], 1);
        s_last = (prev == BLD_BLOCKS - 1);
    }
    __syncthreads();

    // ---- phase 2: last-arriving block scans counts -> cell_start ----
    if (s_last) {
        int lane = tid & 31, wid = tid >> 5;
        int base = tid * 7;                       // 256*7 = 1792 >= 1728
        int v[7]; int s = 0;
        #pragma unroll
        for (int i = 0; i < 7; i++) {
            int c = base + i;
            v[i] = (c < NCELLS) ? g_cell_cnt[c] : 0;
            s += v[i];
        }
        int incl = s;
        #pragma unroll
        for (int o = 1; o < 32; o <<= 1) {
            int nb = __shfl_up_sync(FULLM, incl, o);
            if (lane >= o) incl += nb;
        }
        if (lane == 31) wsum[wid] = incl;
        __syncthreads();
        if (wid == 0 && lane < 8) {
            int ww = wsum[lane];
            int iw = ww;
            #pragma unroll
            for (int o = 1; o < 8; o <<= 1) {
                int nb = __shfl_up_sync(0xffu, iw, o);
                if (lane >= o) iw += nb;
            }
            woff2[lane] = iw - ww;
        }
        __syncthreads();
        int ex = woff2[wid] + incl - s;           // exclusive prefix, first cell
        #pragma unroll
        for (int i = 0; i < 7; i++) {
            int c = base + i;
            if (c < NCELLS) g_cell_start[c] = ex;
            ex += v[i];
        }
        if (tid == BLD_THREADS - 1) g_cell_start[NCELLS] = ex;   // = N_PTS
        __threadfence();
        __syncthreads();
        if (tid == 0) atomicExch(&g_sync[1], 1);
    } else {
        if (tid == 0) {
            while (*((volatile int*)&g_sync[1]) == 0) { __nanosleep(64); }
        }
        __syncthreads();
        __threadfence();
    }

    // ---- phase 3: scatter (no atomic; rank from phase 1) ----
    if (live) {
        int pos = g_cell_start[cell] + rank;
        g_sorted[pos] = make_float4(x, y, z, __int_as_float(n));
    }

    // ---- restore invariants for the next replay ----
    if (n < NCELLS) g_cell_cnt[n] = 0;     // safe: scan already consumed counts
    __syncthreads();
    if (tid == 0) {
        int prev = atomicAdd(&g_sync[2], 1);
        if (prev == BLD_BLOCKS - 1) {      // last build block out resets sync
            atomicExch(&g_sync[0], 0);
            atomicExch(&g_sync[1], 0);
            atomicExch(&g_sync[2], 0);
        }
    }
}

// -------- K2: FUSED query + select + group. One block (128 thr) per query ---
// Candidate scan consumes a CONCATENATED stream over the <=9 cell rows:
// per-warp prefix of row lengths (registers), row lookup via 9 shuffles.
// ~97% lane utilization vs ~54% for per-row chunking. Collection order is
// arbitrary; rank-sort restores ascending original-index order (ids unique).
__global__ __launch_bounds__(128) void fused_kernel(
    const float* __restrict__ new_xyz,
    const float* __restrict__ xyz,
    float* __restrict__ out,
    int write_idn)
{
    __shared__ __align__(16) int s_cand[CAND_MAX];
    __shared__ int s_ids[NSAMP];
    __shared__ int s_cnt;
    __shared__ float4 s_stage[4][NSAMP * 4];     // 2KB per warp

    int tid  = threadIdx.x;
    int w    = tid >> 5;
    int lane = tid & 31;
    int q = blockIdx.x;
    int b = q >> 11;            // NQ_P == 2048
    int p = q & (NQ_P - 1);

    float qx = new_xyz[3 * q], qy = new_xyz[3 * q + 1], qz = new_xyz[3 * q + 2];
    float q2 = sq3(qx, qy, qz);
    const float R2 = R2F;
    const float rp = 0.0801f;   // padded radius for cell coverage

    int x0 = max(0,      (int)floorf((qx - rp) * (float)NC));
    int x1 = min(NC - 1, (int)floorf((qx + rp) * (float)NC));
    int y0 = max(0,      (int)floorf((qy - rp) * (float)NC));
    int y1 = min(NC - 1, (int)floorf((qy + rp) * (float)NC));
    int z0 = max(0,      (int)floorf((qz - rp) * (float)NC));
    int z1 = min(NC - 1, (int)floorf((qz + rp) * (float)NC));

    int ny    = y1 - y0 + 1;                 // <= 3
    int nrows = ny * (z1 - z0 + 1);          // <= 9

    if (tid == 0) s_cnt = 0;
    __syncthreads();

    // ---- per-warp: row ranges (lanes 0..nrows-1) + prefix in registers ----
    int rs0 = 0, rs1 = 0;
    if (lane < nrows) {
        int rz = lane / ny;
        int cy = y0 + (lane - rz * ny);
        int crow = ((z0 + rz) * NC + cy) * NC;
        rs0 = g_cell_start[crow + x0];       // x0..x1 contiguous in sorted
        rs1 = g_cell_start[crow + x1 + 1];
    }
    int len = (lane < nrows) ? (rs1 - rs0) : 0;
    int incl = len;
    #pragma unroll
    for (int o = 1; o < 32; o <<= 1) {
        int nb = __shfl_up_sync(FULLM, incl, o);
        if (lane >= o) incl += nb;
    }
    int T    = __shfl_sync(FULLM, incl, 31);  // total candidates
    int excl = incl - len;                    // per-lane exclusive prefix

    // ---- concatenated candidate scan: block-wide 128-wide chunks ----
    for (int g0 = 32 * w; g0 < T; g0 += 128) {
        int g = g0 + lane;
        bool livec = (g < T);
        int r = 0;
        #pragma unroll
        for (int k = 0; k < 9; k++) {        // row = #rows with incl_k <= g
            int ik = __shfl_sync(FULLM, incl, k);
            r += (g >= ik);
        }
        int j0r = __shfl_sync(FULLM, rs0,  r & 31);
        int exr = __shfl_sync(FULLM, excl, r & 31);
        int j = j0r + (g - exr);
        bool inb = false; int pid = 0;
        if (livec) {
            float4 pt = g_sorted[j];
            float x2  = sq3(pt.x, pt.y, pt.z);
            float dt  = dot3(qx, qy, qz, pt.x, pt.y, pt.z);
            float d2  = __fsub_rn(__fadd_rn(q2, x2), __fmul_rn(2.0f, dt));
            inb = d2 < R2;
            pid = __float_as_int(pt.w);
        }
        unsigned m = __ballot_sync(FULLM, inb);
        int nm = __popc(m);
        int basew = 0;
        if (lane == 0 && nm) basew = atomicAdd(&s_cnt, nm);
        basew = __shfl_sync(FULLM, basew, 0);
        if (inb) {
            int pos = basew + __popc(m & ((1u << lane) - 1u));
            if (pos < CAND_MAX) s_cand[pos] = pid;
        }
    }
    __syncthreads();
    int M = min(s_cnt, CAND_MAX);
    if (tid < 3 && M + tid < CAND_MAX) s_cand[M + tid] = SENT;  // pad for int4
    __syncthreads();

    // ---- rank selection: 128 threads, one candidate each ----
    int v = (tid < M) ? s_cand[tid] : SENT;
    int r = 0;
    {
        const int4* cp4 = reinterpret_cast<const int4*>(s_cand);
        int nj4 = (M + 3) >> 2;
        for (int j4 = 0; j4 < nj4; j4++) {        // broadcast reads
            int4 sv = cp4[j4];
            r += (sv.x < v) + (sv.y < v) + (sv.z < v) + (sv.w < v);
        }
    }
    __syncthreads();                              // reads done before scatter
    if (v != SENT && r < NSAMP) s_ids[r] = v;     // ranks unique (ids unique)
    __syncthreads();

    int cnt = min(M, NSAMP);

    // ---- warp 0: finalize padded ids + xyz channels + idn ----
    size_t ob0 = (((size_t)b * C_OUT) * NQ_P + (size_t)p) * NSAMP;
    const size_t st = (size_t)NQ_P * NSAMP;
    if (w == 0) {
        bool valid = lane < cnt;
        int first = (cnt > 0) ? s_ids[0] : 0;
        int id = valid ? s_ids[lane] : first;
        float idn = (valid || cnt == 0) ? 1.0f : 0.0f;
        __syncwarp();
        s_ids[lane] = id;                         // padded ids for gather warps

        float px = xyz[3 * id], py = xyz[3 * id + 1], pz = xyz[3 * id + 2];
        size_t ob = ob0 + (size_t)lane;
        out[ob]          = __fsub_rn(px, qx);
        out[ob + st]     = __fsub_rn(py, qy);
        out[ob + 2 * st] = __fsub_rn(pz, qz);
        if (write_idn) {
            size_t nfe = (size_t)BATCH * C_OUT * NQ_P * NSAMP;
            out[nfe + (size_t)q * NSAMP + lane] = idn;
        }
    }
    __syncthreads();

    // ---- feature gather: warp w -> channels [16w, 16w+16) ----
    float4* mybuf = s_stage[w];
    int lc = lane & 3;                 // chunk within quarter
    int lr = lane >> 2;                // row base
    #pragma unroll
    for (int t = 0; t < 4; t++) {
        int rr = lr + 8 * t;
        int id_r = s_ids[rr];                       // smem broadcast
        float4 val = g_featT[(size_t)id_r * 16 + 4 * w + lc];
        mybuf[rr * 4 + (lc ^ (rr & 3) ^ ((rr >> 2) & 3))] = val;
    }
    __syncwarp();

    size_t o = ob0 + (size_t)lane + 3 * st;
    int myswz = (lane & 3) ^ ((lane >> 2) & 3);
    #pragma unroll
    for (int j = 0; j < 4; j++) {
        float4 f = mybuf[lane * 4 + (j ^ myswz)];   // channels 4*(4w+j)..+3
        size_t oo = o + (size_t)(4 * (4 * w + j)) * st;
        out[oo]          = f.x;
        out[oo + st]     = f.y;
        out[oo + 2 * st] = f.z;
        out[oo + 3 * st] = f.w;
    }
}

extern "C" void kernel_launch(void* const* d_in, const int* in_sizes, int n_in,
                              void* d_out, int out_size) {
    const float* xyz     = (const float*)d_in[0];   // (20000, 3)
    const float* new_xyz = (const float*)d_in[1];   // (2, 2048, 3)
    const float* feat    = (const float*)d_in[2];   // (64, 20000)
    float* out = (float*)d_out;

    long long nfe = (long long)BATCH * C_OUT * NQ_P * NSAMP;           // 18,350,080
    int write_idn = ((long long)out_size >= nfe + (long long)NQ * NSAMP) ? 1 : 0;

    // Two launches: merged prep (build + transpose overlapped), then fused.
    prep_kernel<<<PREP_BLOCKS, BLD_THREADS>>>(xyz, feat);
    fused_kernel<<<NQ, 128>>>(new_xyz, xyz, out, write_idn);
}